// round 3
// baseline (speedup 1.0000x reference)
#include <cuda_runtime.h>
#include <math.h>
#include <stdint.h>

static constexpr int B_ = 16, C_ = 16, P_ = 512, D_ = 256;

// Scratch (device globals; allocation in kernel_launch is forbidden)
__device__ float g_context[(size_t)B_ * C_ * P_ * D_];   // tf32-rounded
__device__ float g_qr[(size_t)B_ * C_ * P_ * D_];        // tf32-rounded query
__device__ float g_q[(size_t)B_ * C_ * P_ * D_];
__device__ float g_k[(size_t)B_ * C_ * P_ * D_];
__device__ float g_v[(size_t)B_ * C_ * P_ * D_];
__device__ float g_scores[(size_t)B_ * C_ * P_ * P_];
__device__ float g_wq[(size_t)C_ * D_ * D_];             // tf32-rounded weights
__device__ float g_wk[(size_t)C_ * D_ * D_];
__device__ float g_wv[(size_t)C_ * D_ * D_];

// ---------------------------------------------------------------------------
// helpers
// ---------------------------------------------------------------------------
__device__ __forceinline__ void cpasync16(void* smem, const void* gmem) {
    unsigned s = (unsigned)__cvta_generic_to_shared(smem);
    asm volatile("cp.async.cg.shared.global [%0], [%1], 16;\n" :: "r"(s), "l"(gmem));
}
__device__ __forceinline__ float tf32r(float f) {
    uint32_t u; asm("cvt.rna.tf32.f32 %0, %1;" : "=r"(u) : "f"(f));
    return __uint_as_float(u);
}
__device__ __forceinline__ void mma_tf32(float* c, const uint32_t* a, const uint32_t* b) {
    asm volatile(
        "mma.sync.aligned.m16n8k8.row.col.f32.tf32.tf32.f32 "
        "{%0,%1,%2,%3}, {%4,%5,%6,%7}, {%8,%9}, {%0,%1,%2,%3};"
        : "+f"(c[0]), "+f"(c[1]), "+f"(c[2]), "+f"(c[3])
        : "r"(a[0]), "r"(a[1]), "r"(a[2]), "r"(a[3]), "r"(b[0]), "r"(b[1]));
}

// ---------------------------------------------------------------------------
// 0) round weights to tf32 (one pass, 1M elems per weight)
// ---------------------------------------------------------------------------
__global__ void round_weights_kernel(const float* __restrict__ wq,
                                     const float* __restrict__ wk,
                                     const float* __restrict__ wv)
{
    int i = blockIdx.x * blockDim.x + threadIdx.x;     // over n/4
    if (i >= C_ * D_ * D_ / 4) return;
    float4 a = ((const float4*)wq)[i];
    float4 b = ((const float4*)wk)[i];
    float4 c = ((const float4*)wv)[i];
    a.x = tf32r(a.x); a.y = tf32r(a.y); a.z = tf32r(a.z); a.w = tf32r(a.w);
    b.x = tf32r(b.x); b.y = tf32r(b.y); b.z = tf32r(b.z); b.w = tf32r(b.w);
    c.x = tf32r(c.x); c.y = tf32r(c.y); c.z = tf32r(c.z); c.w = tf32r(c.w);
    ((float4*)g_wq)[i] = a;
    ((float4*)g_wk)[i] = b;
    ((float4*)g_wv)[i] = c;
}

// ---------------------------------------------------------------------------
// 1) context = rowsum-over-C(aw*q) - aw*q ; also emit tf32-rounded query
// ---------------------------------------------------------------------------
__global__ void context_kernel(const float* __restrict__ query,
                               const float* __restrict__ aw)
{
    int idx = blockIdx.x * blockDim.x + threadIdx.x;   // over B*P*D
    if (idx >= B_ * P_ * D_) return;
    int b  = idx / (P_ * D_);
    int pd = idx - b * (P_ * D_);

    const float* qb  = query + (size_t)b * C_ * P_ * D_ + pd;
    const float* awp = aw + pd;

    float qv[C_], acw[C_];
    float s = 0.f;
    #pragma unroll
    for (int c = 0; c < C_; c++) {
        float q = qb[(size_t)c * P_ * D_];
        qv[c] = q;
        float v = awp[(size_t)c * P_ * D_] * q;
        acw[c] = v;
        s += v;
    }
    float* ctx = g_context + (size_t)b * C_ * P_ * D_ + pd;
    float* qr  = g_qr + (size_t)b * C_ * P_ * D_ + pd;
    #pragma unroll
    for (int c = 0; c < C_; c++) {
        ctx[(size_t)c * P_ * D_] = tf32r(s - acw[c]);
        qr[(size_t)c * P_ * D_]  = tf32r(qv[c]);
    }
}

// ---------------------------------------------------------------------------
// 2) Batched TF32 tensor-core GEMM. Inputs MUST be pre-rounded to tf32.
//    C[z](M x N) = A[z](M x K, row-major) * B[z % bMod]
//    TRANSB=1: B is (N x K) row-major.  TRANSB=0: B is (K x N) row-major.
//    BM=BN=128, BK=16, 3-stage cp.async pipeline; 8 warps, 64x32 per warp.
//    RELU: v = max(v+bias,0)*scale, output tf32-rounded. Else v*scale, raw.
// ---------------------------------------------------------------------------
template<int K, bool TRANSB, bool RELU>
__global__ __launch_bounds__(256, 2)
void mma_gemm(const float* __restrict__ A0, const float* __restrict__ B0,
              const float* __restrict__ bias0, float* __restrict__ C0,
              int lda, int ldb, int ldc,
              size_t aB, size_t bB, size_t cB, int bMod, float scale)
{
    constexpr int BM = 128, BK = 16;
    constexpr int ASTR  = 20;    // As[m][k] stride
    constexpr int BTSTR = 20;    // Bs[n][k] (TRANSB)
    constexpr int BNSTR = 136;   // Bs[k][n] (no trans)
    constexpr int STG   = 2560;  // floats per stage per operand

    extern __shared__ float sm[];
    float* As = sm;              // 3 stages x 2560
    float* Bs = sm + 3 * STG;    // 3 stages x 2560

    const int tid  = threadIdx.x;
    const int lane = tid & 31;
    const int warp = tid >> 5;
    const int wm = warp >> 2;          // 0..1
    const int wn = warp & 3;           // 0..3
    const int z  = blockIdx.z;
    const int m_blk = blockIdx.x * BM;
    const int n_blk = blockIdx.y * 128;

    const float* Ap = A0 + (size_t)z * aB + (size_t)m_blk * lda;
    const float* Bp = B0 + (size_t)(z % bMod) * bB;

    float acc[4][4][4];
    #pragma unroll
    for (int i = 0; i < 4; i++)
        #pragma unroll
        for (int j = 0; j < 4; j++)
            #pragma unroll
            for (int r = 0; r < 4; r++) acc[i][j][r] = 0.f;

    const int arow = tid >> 2;         // 0..63
    const int aq   = (tid & 3) * 4;    // 0,4,8,12

    auto load_tile = [&](int k0, int buf) {
        float* Asb = As + buf * STG;
        float* Bsb = Bs + buf * STG;
        #pragma unroll
        for (int i = 0; i < 2; i++) {
            int r = arow + i * 64;
            cpasync16(&Asb[r * ASTR + aq], Ap + (size_t)r * lda + k0 + aq);
        }
        if (TRANSB) {
            #pragma unroll
            for (int i = 0; i < 2; i++) {
                int r = arow + i * 64;
                cpasync16(&Bsb[r * BTSTR + aq],
                          Bp + (size_t)(n_blk + r) * ldb + k0 + aq);
            }
        } else {
            int kr = tid >> 5;
            int nq = (tid & 31) * 4;
            #pragma unroll
            for (int i = 0; i < 2; i++) {
                int kk = kr + i * 8;
                cpasync16(&Bsb[kk * BNSTR + nq],
                          Bp + (size_t)(k0 + kk) * ldb + n_blk + nq);
            }
        }
        asm volatile("cp.async.commit_group;\n");
    };

    constexpr int NT = K / BK;
    load_tile(0, 0);
    load_tile(BK, 1);

    // hoisted fragment addresses (warp/lane constant)
    const int aoff  = (wm * 64 + (lane >> 2)) * ASTR + (lane & 3);
    const int btoff = (wn * 32 + (lane >> 2)) * BTSTR + (lane & 3);
    const int bnoff = (lane & 3) * BNSTR + wn * 32 + (lane >> 2);

    #pragma unroll 1
    for (int t = 0; t < NT; t++) {
        if (t + 2 < NT) {
            load_tile((t + 2) * BK, (t + 2) % 3);
            asm volatile("cp.async.wait_group 2;\n");
        } else if (t + 1 < NT) {
            asm volatile("cp.async.wait_group 1;\n");
        } else {
            asm volatile("cp.async.wait_group 0;\n");
        }
        __syncthreads();

        const float* Asb = As + (t % 3) * STG;
        const float* Bsb = Bs + (t % 3) * STG;

        #pragma unroll
        for (int ks = 0; ks < BK; ks += 8) {
            uint32_t afr[4][4];
            #pragma unroll
            for (int i = 0; i < 4; i++) {
                const float* p = Asb + aoff + i * (16 * ASTR) + ks;
                afr[i][0] = __float_as_uint(p[0]);
                afr[i][1] = __float_as_uint(p[8 * ASTR]);
                afr[i][2] = __float_as_uint(p[4]);
                afr[i][3] = __float_as_uint(p[8 * ASTR + 4]);
            }
            uint32_t bfr[4][2];
            #pragma unroll
            for (int j = 0; j < 4; j++) {
                if (TRANSB) {
                    const float* p = Bsb + btoff + j * (8 * BTSTR) + ks;
                    bfr[j][0] = __float_as_uint(p[0]);
                    bfr[j][1] = __float_as_uint(p[4]);
                } else {
                    const float* p = Bsb + bnoff + ks * BNSTR + j * 8;
                    bfr[j][0] = __float_as_uint(p[0]);
                    bfr[j][1] = __float_as_uint(p[4 * BNSTR]);
                }
            }
            #pragma unroll
            for (int i = 0; i < 4; i++)
                #pragma unroll
                for (int j = 0; j < 4; j++)
                    mma_tf32(acc[i][j], afr[i], bfr[j]);
        }
        __syncthreads();
    }

    // epilogue
    float* Cbase = C0 + (size_t)z * cB;
    #pragma unroll
    for (int j = 0; j < 4; j++) {
        int cidx = n_blk + wn * 32 + j * 8 + 2 * (lane & 3);
        float b0 = 0.f, b1 = 0.f;
        if (RELU) {
            const float* bp = bias0 + (size_t)(z % bMod) * D_ + cidx;
            b0 = bp[0]; b1 = bp[1];
        }
        #pragma unroll
        for (int i = 0; i < 4; i++) {
            int r0 = m_blk + wm * 64 + i * 16 + (lane >> 2);
            float v0 = acc[i][j][0], v1 = acc[i][j][1];
            float v2 = acc[i][j][2], v3 = acc[i][j][3];
            if (RELU) {
                v0 = tf32r(fmaxf(v0 + b0, 0.f) * scale);
                v1 = tf32r(fmaxf(v1 + b1, 0.f) * scale);
                v2 = tf32r(fmaxf(v2 + b0, 0.f) * scale);
                v3 = tf32r(fmaxf(v3 + b1, 0.f) * scale);
            } else {
                v0 *= scale; v1 *= scale; v2 *= scale; v3 *= scale;
            }
            *(float2*)(Cbase + (size_t)r0 * ldc + cidx)       = make_float2(v0, v1);
            *(float2*)(Cbase + (size_t)(r0 + 8) * ldc + cidx) = make_float2(v2, v3);
        }
    }
}

// ---------------------------------------------------------------------------
// 3) Softmax over rows of g_scores (row length 512), output tf32-rounded.
// ---------------------------------------------------------------------------
__global__ void softmax_kernel()
{
    int gw   = (blockIdx.x * blockDim.x + threadIdx.x) >> 5;
    int lane = threadIdx.x & 31;
    if (gw >= B_ * C_ * P_) return;

    float4* row = reinterpret_cast<float4*>(g_scores) + (size_t)gw * (P_ / 4);

    float4 v[4];
    float m = -1e30f;
    #pragma unroll
    for (int i = 0; i < 4; i++) {
        v[i] = row[lane + 32 * i];
        m = fmaxf(m, fmaxf(fmaxf(v[i].x, v[i].y), fmaxf(v[i].z, v[i].w)));
    }
    #pragma unroll
    for (int o = 16; o > 0; o >>= 1)
        m = fmaxf(m, __shfl_xor_sync(0xffffffffu, m, o));

    float s = 0.f;
    #pragma unroll
    for (int i = 0; i < 4; i++) {
        v[i].x = __expf(v[i].x - m);
        v[i].y = __expf(v[i].y - m);
        v[i].z = __expf(v[i].z - m);
        v[i].w = __expf(v[i].w - m);
        s += v[i].x + v[i].y + v[i].z + v[i].w;
    }
    #pragma unroll
    for (int o = 16; o > 0; o >>= 1)
        s += __shfl_xor_sync(0xffffffffu, s, o);

    float inv = 1.0f / s;
    #pragma unroll
    for (int i = 0; i < 4; i++) {
        v[i].x = tf32r(v[i].x * inv); v[i].y = tf32r(v[i].y * inv);
        v[i].z = tf32r(v[i].z * inv); v[i].w = tf32r(v[i].w * inv);
        row[lane + 32 * i] = v[i];
    }
}

// ---------------------------------------------------------------------------
// launch
// ---------------------------------------------------------------------------
extern "C" void kernel_launch(void* const* d_in, const int* in_sizes, int n_in,
                              void* d_out, int out_size)
{
    const float* query = (const float*)d_in[0];
    const float* aw    = (const float*)d_in[1];
    const float* wq    = (const float*)d_in[2];
    const float* wk    = (const float*)d_in[3];
    const float* wv    = (const float*)d_in[4];
    const float* bq    = (const float*)d_in[5];
    const float* bk    = (const float*)d_in[6];
    const float* bv    = (const float*)d_in[7];
    float* out = (float*)d_out;

    float *gctx, *gqr, *gq, *gk, *gv, *gsc, *gwq, *gwk, *gwv;
    cudaGetSymbolAddress((void**)&gctx, g_context);
    cudaGetSymbolAddress((void**)&gqr, g_qr);
    cudaGetSymbolAddress((void**)&gq, g_q);
    cudaGetSymbolAddress((void**)&gk, g_k);
    cudaGetSymbolAddress((void**)&gv, g_v);
    cudaGetSymbolAddress((void**)&gsc, g_scores);
    cudaGetSymbolAddress((void**)&gwq, g_wq);
    cudaGetSymbolAddress((void**)&gwk, g_wk);
    cudaGetSymbolAddress((void**)&gwv, g_wv);

    constexpr int SMEM_BYTES = 3 * 2560 * 2 * 4;   // 61440
    cudaFuncSetAttribute(mma_gemm<D_, false, true>,
        cudaFuncAttributeMaxDynamicSharedMemorySize, SMEM_BYTES);
    cudaFuncSetAttribute(mma_gemm<D_, true, false>,
        cudaFuncAttributeMaxDynamicSharedMemorySize, SMEM_BYTES);
    cudaFuncSetAttribute(mma_gemm<P_, false, false>,
        cudaFuncAttributeMaxDynamicSharedMemorySize, SMEM_BYTES);

    const float qscale = 1.0f / 16.0f;   // D^-0.5
    const size_t PD = (size_t)P_ * D_;
    const size_t PP = (size_t)P_ * P_;
    const size_t DD = (size_t)D_ * D_;

    // 0) round weights once per launch (deterministic, capturable)
    round_weights_kernel<<<(C_ * D_ * D_ / 4 + 255) / 256, 256>>>(wq, wk, wv);

    // 1) context (+ rounded query copy)
    context_kernel<<<(B_ * P_ * D_) / 256, 256>>>(query, aw);

    // 2) projections: per (b,c) GEMM 512 x 256 x 256, bias+relu (+scale for q)
    dim3 gp(4, 2, B_ * C_);
    mma_gemm<D_, false, true><<<gp, 256, SMEM_BYTES>>>(gqr, gwq, bq, gq,
        D_, D_, D_, PD, DD, PD, C_, qscale);
    mma_gemm<D_, false, true><<<gp, 256, SMEM_BYTES>>>(gctx, gwk, bk, gk,
        D_, D_, D_, PD, DD, PD, C_, 1.0f);
    mma_gemm<D_, false, true><<<gp, 256, SMEM_BYTES>>>(gctx, gwv, bv, gv,
        D_, D_, D_, PD, DD, PD, C_, 1.0f);

    // 3) scores = q @ k^T  per (b,c): 512 x 512 x 256
    dim3 gs(4, 4, B_ * C_);
    mma_gemm<D_, true, false><<<gs, 256, SMEM_BYTES>>>(gq, gk, nullptr, gsc,
        D_, D_, P_, PD, PD, PP, B_ * C_, 1.0f);

    // 4) softmax in-place on scores (rounds attn to tf32)
    softmax_kernel<<<(B_ * C_ * P_) / 8, 256>>>();

    // 5) out = attn @ v  per (b,c): 512 x 256 x 512
    dim3 go(4, 2, B_ * C_);
    mma_gemm<P_, false, false><<<go, 256, SMEM_BYTES>>>(gsc, gv, nullptr, out,
        P_, D_, D_, PP, PD, PD, B_ * C_, 1.0f);
}

// round 6
// speedup vs baseline: 1.0532x; 1.0532x over previous
#include <cuda_runtime.h>
#include <math.h>
#include <stdint.h>

static constexpr int B_ = 16, C_ = 16, P_ = 512, D_ = 256;

// Scratch (device globals; allocation in kernel_launch is forbidden)
__device__ float g_context[(size_t)B_ * C_ * P_ * D_];   // tf32-rounded
__device__ float g_qr[(size_t)B_ * C_ * P_ * D_];        // tf32-rounded query
__device__ float g_q[(size_t)B_ * C_ * P_ * D_];
__device__ float g_k[(size_t)B_ * C_ * P_ * D_];
__device__ float g_v[(size_t)B_ * C_ * P_ * D_];
__device__ float g_scores[(size_t)B_ * C_ * P_ * P_];
__device__ float g_wq[(size_t)C_ * D_ * D_];             // tf32-rounded weights
__device__ float g_wk[(size_t)C_ * D_ * D_];
__device__ float g_wv[(size_t)C_ * D_ * D_];

// ---------------------------------------------------------------------------
// helpers
// ---------------------------------------------------------------------------
__device__ __forceinline__ void cpasync16(void* smem, const void* gmem) {
    unsigned s = (unsigned)__cvta_generic_to_shared(smem);
    asm volatile("cp.async.cg.shared.global [%0], [%1], 16;\n" :: "r"(s), "l"(gmem));
}
__device__ __forceinline__ float tf32r(float f) {
    uint32_t u; asm("cvt.rna.tf32.f32 %0, %1;" : "=r"(u) : "f"(f));
    return __uint_as_float(u);
}
__device__ __forceinline__ void mma_tf32(float* c, const uint32_t* a, const uint32_t* b) {
    asm volatile(
        "mma.sync.aligned.m16n8k8.row.col.f32.tf32.tf32.f32 "
        "{%0,%1,%2,%3}, {%4,%5,%6,%7}, {%8,%9}, {%0,%1,%2,%3};"
        : "+f"(c[0]), "+f"(c[1]), "+f"(c[2]), "+f"(c[3])
        : "r"(a[0]), "r"(a[1]), "r"(a[2]), "r"(a[3]), "r"(b[0]), "r"(b[1]));
}

// ---------------------------------------------------------------------------
// 0) round weights to tf32 (one pass)
// ---------------------------------------------------------------------------
__global__ void round_weights_kernel(const float* __restrict__ wq,
                                     const float* __restrict__ wk,
                                     const float* __restrict__ wv)
{
    int i = blockIdx.x * blockDim.x + threadIdx.x;     // over n/4
    if (i >= C_ * D_ * D_ / 4) return;
    float4 a = ((const float4*)wq)[i];
    float4 b = ((const float4*)wk)[i];
    float4 c = ((const float4*)wv)[i];
    a.x = tf32r(a.x); a.y = tf32r(a.y); a.z = tf32r(a.z); a.w = tf32r(a.w);
    b.x = tf32r(b.x); b.y = tf32r(b.y); b.z = tf32r(b.z); b.w = tf32r(b.w);
    c.x = tf32r(c.x); c.y = tf32r(c.y); c.z = tf32r(c.z); c.w = tf32r(c.w);
    ((float4*)g_wq)[i] = a;
    ((float4*)g_wk)[i] = b;
    ((float4*)g_wv)[i] = c;
}

// ---------------------------------------------------------------------------
// 1) context = rowsum-over-C(aw*q) - aw*q ; also emit tf32-rounded query
// ---------------------------------------------------------------------------
__global__ void context_kernel(const float* __restrict__ query,
                               const float* __restrict__ aw)
{
    int idx = blockIdx.x * blockDim.x + threadIdx.x;   // over B*P*D
    if (idx >= B_ * P_ * D_) return;
    int b  = idx / (P_ * D_);
    int pd = idx - b * (P_ * D_);

    const float* qb  = query + (size_t)b * C_ * P_ * D_ + pd;
    const float* awp = aw + pd;

    float qv[C_], acw[C_];
    float s = 0.f;
    #pragma unroll
    for (int c = 0; c < C_; c++) {
        float q = qb[(size_t)c * P_ * D_];
        qv[c] = q;
        float v = awp[(size_t)c * P_ * D_] * q;
        acw[c] = v;
        s += v;
    }
    float* ctx = g_context + (size_t)b * C_ * P_ * D_ + pd;
    float* qr  = g_qr + (size_t)b * C_ * P_ * D_ + pd;
    #pragma unroll
    for (int c = 0; c < C_; c++) {
        ctx[(size_t)c * P_ * D_] = tf32r(s - acw[c]);
        qr[(size_t)c * P_ * D_]  = tf32r(qv[c]);
    }
}

// ---------------------------------------------------------------------------
// 2) Batched TF32 tensor-core GEMM, 64x64 warp tiles. Inputs pre-rounded tf32.
//    C[z](M x N) = A[z](M x K, row-major) * B[z % bMod]
//    TRANSB=1: B is (N x K) row-major.  TRANSB=0: B is (K x N) row-major.
//    CTA 128x128, BK=16, 3-stage cp.async; 4 warps (2x2), 64x64 per warp:
//    per k=8 step each warp issues 32 LDS / 32 MMA (was 24/16).
// ---------------------------------------------------------------------------
template<int K, bool TRANSB, bool RELU>
__global__ __launch_bounds__(128, 2)
void mma_gemm(const float* __restrict__ A0, const float* __restrict__ B0,
              const float* __restrict__ bias0, float* __restrict__ C0,
              int lda, int ldb, int ldc,
              size_t aB, size_t bB, size_t cB, int bMod, float scale)
{
    constexpr int BK = 16;
    constexpr int ASTR  = 20;    // As[m][k] stride
    constexpr int BTSTR = 20;    // Bs[n][k] (TRANSB)
    constexpr int BNSTR = 136;   // Bs[k][n] (no trans)
    constexpr int STG   = 2560;  // floats per stage per operand

    extern __shared__ float sm[];
    float* As = sm;              // 3 stages x 2560
    float* Bs = sm + 3 * STG;    // 3 stages x 2560

    const int tid  = threadIdx.x;
    const int lane = tid & 31;
    const int warp = tid >> 5;           // 0..3
    const int wm = warp >> 1;            // 0..1
    const int wn = warp & 1;             // 0..1
    const int z  = blockIdx.z;
    const int m_blk = blockIdx.x * 128;
    const int n_blk = blockIdx.y * 128;

    const float* Ap = A0 + (size_t)z * aB + (size_t)m_blk * lda;
    const float* Bp = B0 + (size_t)(z % bMod) * bB;

    float acc[4][8][4];
    #pragma unroll
    for (int i = 0; i < 4; i++)
        #pragma unroll
        for (int j = 0; j < 8; j++)
            #pragma unroll
            for (int r = 0; r < 4; r++) acc[i][j][r] = 0.f;

    const int arow = tid >> 2;           // 0..31
    const int aq   = (tid & 3) * 4;      // 0,4,8,12

    auto load_tile = [&](int k0, int buf) {
        float* Asb = As + buf * STG;
        float* Bsb = Bs + buf * STG;
        #pragma unroll
        for (int i = 0; i < 4; i++) {
            int r = arow + 32 * i;
            cpasync16(&Asb[r * ASTR + aq], Ap + (size_t)r * lda + k0 + aq);
        }
        if (TRANSB) {
            #pragma unroll
            for (int i = 0; i < 4; i++) {
                int r = arow + 32 * i;
                cpasync16(&Bsb[r * BTSTR + aq],
                          Bp + (size_t)(n_blk + r) * ldb + k0 + aq);
            }
        } else {
            int kr = tid >> 5;               // 0..3
            int nq = (tid & 31) * 4;         // 0..124
            #pragma unroll
            for (int i = 0; i < 4; i++) {
                int kk = kr + 4 * i;         // 0..15
                cpasync16(&Bsb[kk * BNSTR + nq],
                          Bp + (size_t)(k0 + kk) * ldb + n_blk + nq);
            }
        }
        asm volatile("cp.async.commit_group;\n");
    };

    constexpr int NT = K / BK;
    load_tile(0, 0);
    load_tile(BK, 1);

    // hoisted fragment base offsets (warp/lane constant)
    const int aoff  = (wm * 64 + (lane >> 2)) * ASTR + (lane & 3);
    const int btoff = (wn * 64 + (lane >> 2)) * BTSTR + (lane & 3);
    const int bnoff = (lane & 3) * BNSTR + wn * 64 + (lane >> 2);

    #pragma unroll 1
    for (int t = 0; t < NT; t++) {
        if (t + 2 < NT) {
            load_tile((t + 2) * BK, (t + 2) % 3);
            asm volatile("cp.async.wait_group 2;\n");
        } else if (t + 1 < NT) {
            asm volatile("cp.async.wait_group 1;\n");
        } else {
            asm volatile("cp.async.wait_group 0;\n");
        }
        __syncthreads();

        const float* Asb = As + (t % 3) * STG;
        const float* Bsb = Bs + (t % 3) * STG;

        #pragma unroll
        for (int ks = 0; ks < BK; ks += 8) {
            uint32_t afr[4][4];
            #pragma unroll
            for (int i = 0; i < 4; i++) {
                const float* p = Asb + aoff + i * (16 * ASTR) + ks;
                afr[i][0] = __float_as_uint(p[0]);
                afr[i][1] = __float_as_uint(p[8 * ASTR]);
                afr[i][2] = __float_as_uint(p[4]);
                afr[i][3] = __float_as_uint(p[8 * ASTR + 4]);
            }
            uint32_t bfr[8][2];
            #pragma unroll
            for (int j = 0; j < 8; j++) {
                if (TRANSB) {
                    const float* p = Bsb + btoff + j * (8 * BTSTR) + ks;
                    bfr[j][0] = __float_as_uint(p[0]);
                    bfr[j][1] = __float_as_uint(p[4]);
                } else {
                    const float* p = Bsb + bnoff + ks * BNSTR + j * 8;
                    bfr[j][0] = __float_as_uint(p[0]);
                    bfr[j][1] = __float_as_uint(p[4 * BNSTR]);
                }
            }
            #pragma unroll
            for (int i = 0; i < 4; i++)
                #pragma unroll
                for (int j = 0; j < 8; j++)
                    mma_tf32(acc[i][j], afr[i], bfr[j]);
        }
        __syncthreads();
    }

    // epilogue
    float* Cbase = C0 + (size_t)z * cB;
    #pragma unroll
    for (int j = 0; j < 8; j++) {
        int cidx = n_blk + wn * 64 + j * 8 + 2 * (lane & 3);
        float b0 = 0.f, b1 = 0.f;
        if (RELU) {
            const float* bp = bias0 + (size_t)(z % bMod) * D_ + cidx;
            b0 = bp[0]; b1 = bp[1];
        }
        #pragma unroll
        for (int i = 0; i < 4; i++) {
            int r0 = m_blk + wm * 64 + i * 16 + (lane >> 2);
            float v0 = acc[i][j][0], v1 = acc[i][j][1];
            float v2 = acc[i][j][2], v3 = acc[i][j][3];
            if (RELU) {
                v0 = tf32r(fmaxf(v0 + b0, 0.f) * scale);
                v1 = tf32r(fmaxf(v1 + b1, 0.f) * scale);
                v2 = tf32r(fmaxf(v2 + b0, 0.f) * scale);
                v3 = tf32r(fmaxf(v3 + b1, 0.f) * scale);
            } else {
                v0 *= scale; v1 *= scale; v2 *= scale; v3 *= scale;
            }
            *(float2*)(Cbase + (size_t)r0 * ldc + cidx)       = make_float2(v0, v1);
            *(float2*)(Cbase + (size_t)(r0 + 8) * ldc + cidx) = make_float2(v2, v3);
        }
    }
}

// ---------------------------------------------------------------------------
// 3) Softmax over rows of g_scores (row length 512), output tf32-rounded.
// ---------------------------------------------------------------------------
__global__ void softmax_kernel()
{
    int gw   = (blockIdx.x * blockDim.x + threadIdx.x) >> 5;
    int lane = threadIdx.x & 31;
    if (gw >= B_ * C_ * P_) return;

    float4* row = reinterpret_cast<float4*>(g_scores) + (size_t)gw * (P_ / 4);

    float4 v[4];
    float m = -1e30f;
    #pragma unroll
    for (int i = 0; i < 4; i++) {
        v[i] = row[lane + 32 * i];
        m = fmaxf(m, fmaxf(fmaxf(v[i].x, v[i].y), fmaxf(v[i].z, v[i].w)));
    }
    #pragma unroll
    for (int o = 16; o > 0; o >>= 1)
        m = fmaxf(m, __shfl_xor_sync(0xffffffffu, m, o));

    float s = 0.f;
    #pragma unroll
    for (int i = 0; i < 4; i++) {
        v[i].x = __expf(v[i].x - m);
        v[i].y = __expf(v[i].y - m);
        v[i].z = __expf(v[i].z - m);
        v[i].w = __expf(v[i].w - m);
        s += v[i].x + v[i].y + v[i].z + v[i].w;
    }
    #pragma unroll
    for (int o = 16; o > 0; o >>= 1)
        s += __shfl_xor_sync(0xffffffffu, s, o);

    float inv = 1.0f / s;
    #pragma unroll
    for (int i = 0; i < 4; i++) {
        v[i].x = tf32r(v[i].x * inv); v[i].y = tf32r(v[i].y * inv);
        v[i].z = tf32r(v[i].z * inv); v[i].w = tf32r(v[i].w * inv);
        row[lane + 32 * i] = v[i];
    }
}

// ---------------------------------------------------------------------------
// launch
// ---------------------------------------------------------------------------
extern "C" void kernel_launch(void* const* d_in, const int* in_sizes, int n_in,
                              void* d_out, int out_size)
{
    const float* query = (const float*)d_in[0];
    const float* aw    = (const float*)d_in[1];
    const float* wq    = (const float*)d_in[2];
    const float* wk    = (const float*)d_in[3];
    const float* wv    = (const float*)d_in[4];
    const float* bq    = (const float*)d_in[5];
    const float* bk    = (const float*)d_in[6];
    const float* bv    = (const float*)d_in[7];
    float* out = (float*)d_out;

    float *gctx, *gqr, *gq, *gk, *gv, *gsc, *gwq, *gwk, *gwv;
    cudaGetSymbolAddress((void**)&gctx, g_context);
    cudaGetSymbolAddress((void**)&gqr, g_qr);
    cudaGetSymbolAddress((void**)&gq, g_q);
    cudaGetSymbolAddress((void**)&gk, g_k);
    cudaGetSymbolAddress((void**)&gv, g_v);
    cudaGetSymbolAddress((void**)&gsc, g_scores);
    cudaGetSymbolAddress((void**)&gwq, g_wq);
    cudaGetSymbolAddress((void**)&gwk, g_wk);
    cudaGetSymbolAddress((void**)&gwv, g_wv);

    constexpr int SMEM_BYTES = 3 * 2560 * 2 * 4;   // 61440
    cudaFuncSetAttribute(mma_gemm<D_, false, true>,
        cudaFuncAttributeMaxDynamicSharedMemorySize, SMEM_BYTES);
    cudaFuncSetAttribute(mma_gemm<D_, true, false>,
        cudaFuncAttributeMaxDynamicSharedMemorySize, SMEM_BYTES);
    cudaFuncSetAttribute(mma_gemm<P_, false, false>,
        cudaFuncAttributeMaxDynamicSharedMemorySize, SMEM_BYTES);

    const float qscale = 1.0f / 16.0f;   // D^-0.5
    const size_t PD = (size_t)P_ * D_;
    const size_t PP = (size_t)P_ * P_;
    const size_t DD = (size_t)D_ * D_;

    // 0) round weights once (deterministic, capturable)
    round_weights_kernel<<<(C_ * D_ * D_ / 4 + 255) / 256, 256>>>(wq, wk, wv);

    // 1) context (+ rounded query copy)
    context_kernel<<<(B_ * P_ * D_) / 256, 256>>>(query, aw);

    // 2) projections: per (b,c) GEMM 512 x 256 x 256, bias+relu (+scale for q)
    dim3 gp(4, 2, B_ * C_);
    mma_gemm<D_, false, true><<<gp, 128, SMEM_BYTES>>>(gqr, gwq, bq, gq,
        D_, D_, D_, PD, DD, PD, C_, qscale);
    mma_gemm<D_, false, true><<<gp, 128, SMEM_BYTES>>>(gctx, gwk, bk, gk,
        D_, D_, D_, PD, DD, PD, C_, 1.0f);
    mma_gemm<D_, false, true><<<gp, 128, SMEM_BYTES>>>(gctx, gwv, bv, gv,
        D_, D_, D_, PD, DD, PD, C_, 1.0f);

    // 3) scores = q @ k^T  per (b,c): 512 x 512 x 256
    dim3 gs(4, 4, B_ * C_);
    mma_gemm<D_, true, false><<<gs, 128, SMEM_BYTES>>>(gq, gk, nullptr, gsc,
        D_, D_, P_, PD, PD, PP, B_ * C_, 1.0f);

    // 4) softmax in-place on scores (rounds attn to tf32)
    softmax_kernel<<<(B_ * C_ * P_) / 8, 256>>>();

    // 5) out = attn @ v  per (b,c): 512 x 256 x 512
    dim3 go(4, 2, B_ * C_);
    mma_gemm<P_, false, false><<<go, 128, SMEM_BYTES>>>(gsc, gv, nullptr, out,
        P_, D_, D_, PP, PD, PD, B_ * C_, 1.0f);
}

// round 7
// speedup vs baseline: 1.7617x; 1.6728x over previous
#include <cuda_runtime.h>
#include <cuda_bf16.h>
#include <math.h>
#include <stdint.h>

static constexpr int B_ = 16, C_ = 16, P_ = 512, D_ = 256;

// Scratch (device globals; allocation in kernel_launch is forbidden)
__device__ __nv_bfloat16 g_context[(size_t)B_ * C_ * P_ * D_];  // [b,c][p][d]
__device__ __nv_bfloat16 g_qr[(size_t)B_ * C_ * P_ * D_];       // [b,c][p][d]
__device__ __nv_bfloat16 g_q[(size_t)B_ * C_ * P_ * D_];        // [b,c][p][e]
__device__ __nv_bfloat16 g_k[(size_t)B_ * C_ * P_ * D_];        // [b,c][p][e]
__device__ __nv_bfloat16 g_vT[(size_t)B_ * C_ * P_ * D_];       // [b,c][e][p]
__device__ __nv_bfloat16 g_scores[(size_t)B_ * C_ * P_ * P_];   // [b,c][p][q]
__device__ __nv_bfloat16 g_wqT[(size_t)C_ * D_ * D_];           // [c][e][d]
__device__ __nv_bfloat16 g_wkT[(size_t)C_ * D_ * D_];
__device__ __nv_bfloat16 g_wvT[(size_t)C_ * D_ * D_];

// ---------------------------------------------------------------------------
// helpers
// ---------------------------------------------------------------------------
__device__ __forceinline__ void cpasync16(void* smem, const void* gmem) {
    unsigned s = (unsigned)__cvta_generic_to_shared(smem);
    asm volatile("cp.async.cg.shared.global [%0], [%1], 16;\n" :: "r"(s), "l"(gmem));
}
__device__ __forceinline__ void mma_bf16(float* c, const uint32_t* a, const uint32_t* b) {
    asm volatile(
        "mma.sync.aligned.m16n8k16.row.col.f32.bf16.bf16.f32 "
        "{%0,%1,%2,%3}, {%4,%5,%6,%7}, {%8,%9}, {%0,%1,%2,%3};"
        : "+f"(c[0]), "+f"(c[1]), "+f"(c[2]), "+f"(c[3])
        : "r"(a[0]), "r"(a[1]), "r"(a[2]), "r"(a[3]), "r"(b[0]), "r"(b[1]));
}
__device__ __forceinline__ uint32_t packbf(float x, float y) {
    __nv_bfloat162 h = __floats2bfloat162_rn(x, y);
    return *(uint32_t*)&h;
}

// ---------------------------------------------------------------------------
// 0) transpose weights to bf16 [c][e][d]
// ---------------------------------------------------------------------------
__global__ void transpose_w_kernel(const float* __restrict__ wq,
                                   const float* __restrict__ wk,
                                   const float* __restrict__ wv)
{
    __shared__ float tile[32][33];
    int which = blockIdx.z / C_;
    int c     = blockIdx.z % C_;
    const float* src = (which == 0) ? wq : (which == 1) ? wk : wv;
    __nv_bfloat16* dst = (which == 0) ? g_wqT : (which == 1) ? g_wkT : g_wvT;
    src += (size_t)c * D_ * D_;
    dst += (size_t)c * D_ * D_;

    int x0 = blockIdx.x * 32;   // d
    int y0 = blockIdx.y * 32;   // e
    int tx = threadIdx.x, ty = threadIdx.y;
    #pragma unroll
    for (int j = 0; j < 4; j++)
        tile[ty + 8 * j][tx] = src[(size_t)(x0 + ty + 8 * j) * D_ + y0 + tx];
    __syncthreads();
    #pragma unroll
    for (int j = 0; j < 4; j++)
        dst[(size_t)(y0 + ty + 8 * j) * D_ + x0 + tx] =
            __float2bfloat16(tile[tx][ty + 8 * j]);
}

// ---------------------------------------------------------------------------
// 1) context = rowsum-over-C(aw*q) - aw*q, bf16 out; also bf16 query copy
// ---------------------------------------------------------------------------
__global__ void context_kernel(const float* __restrict__ query,
                               const float* __restrict__ aw)
{
    int idx = blockIdx.x * blockDim.x + threadIdx.x;   // over B*P*D/2 (pairs)
    if (idx >= B_ * P_ * D_ / 2) return;
    int b  = idx / (P_ * D_ / 2);
    int pd = (idx - b * (P_ * D_ / 2)) * 2;

    const float* qb  = query + (size_t)b * C_ * P_ * D_ + pd;
    const float* awp = aw + pd;

    float q0[C_], q1[C_], a0[C_], a1[C_];
    float s0 = 0.f, s1 = 0.f;
    #pragma unroll
    for (int c = 0; c < C_; c++) {
        float2 q = *(const float2*)(qb + (size_t)c * P_ * D_);
        float2 w = *(const float2*)(awp + (size_t)c * P_ * D_);
        q0[c] = q.x; q1[c] = q.y;
        a0[c] = w.x * q.x; a1[c] = w.y * q.y;
        s0 += a0[c]; s1 += a1[c];
    }
    __nv_bfloat16* ctx = g_context + (size_t)b * C_ * P_ * D_ + pd;
    __nv_bfloat16* qr  = g_qr + (size_t)b * C_ * P_ * D_ + pd;
    #pragma unroll
    for (int c = 0; c < C_; c++) {
        *(uint32_t*)(ctx + (size_t)c * P_ * D_) = packbf(s0 - a0[c], s1 - a1[c]);
        *(uint32_t*)(qr + (size_t)c * P_ * D_)  = packbf(q0[c], q1[c]);
    }
}

// ---------------------------------------------------------------------------
// 2) Unified batched bf16 GEMM: C[z] = A[z%aMod](MxK) * B[z%bMod](NxK)^T
//    All operands bf16 k-major. CTA 128x128, BK=32, 3-stage cp.async,
//    4 warps, 64x64 warp tile, m16n8k16.
//    MODE 0: bf16 store. MODE 1: col-bias+relu+scale, bf16. MODE 2: row-bias
//    +relu, bf16. MODE 3: fp32 store.
// ---------------------------------------------------------------------------
template<int K, int MODE>
__global__ __launch_bounds__(128, 2)
void mma_gemm(const __nv_bfloat16* __restrict__ A0,
              const __nv_bfloat16* __restrict__ B0,
              const float* __restrict__ bias0, void* __restrict__ C0,
              int lda, int ldb, int ldc,
              size_t aB, size_t bB, size_t cB,
              int aMod, int bMod, float scale)
{
    constexpr int BK = 32;
    constexpr int SA = 40;                 // bf16 elems per smem row (pad 8)
    constexpr int STG = 128 * SA;          // per operand per stage

    extern __shared__ __nv_bfloat16 sh[];
    __nv_bfloat16* As = sh;                // 3 stages
    __nv_bfloat16* Bs = sh + 3 * STG;

    const int tid  = threadIdx.x;
    const int lane = tid & 31;
    const int warp = tid >> 5;             // 0..3
    const int wm = warp >> 1;              // 0..1
    const int wn = warp & 1;               // 0..1
    const int z  = blockIdx.z;
    const int m_blk = blockIdx.x * 128;
    const int n_blk = blockIdx.y * 128;

    const __nv_bfloat16* Ap = A0 + (size_t)(z % aMod) * aB + (size_t)m_blk * lda;
    const __nv_bfloat16* Bp = B0 + (size_t)(z % bMod) * bB + (size_t)n_blk * ldb;

    float acc[4][8][4];
    #pragma unroll
    for (int i = 0; i < 4; i++)
        #pragma unroll
        for (int j = 0; j < 8; j++)
            #pragma unroll
            for (int r = 0; r < 4; r++) acc[i][j][r] = 0.f;

    auto load_tile = [&](int k0, int buf) {
        __nv_bfloat16* Asb = As + buf * STG;
        __nv_bfloat16* Bsb = Bs + buf * STG;
        #pragma unroll
        for (int i = 0; i < 4; i++) {
            int idx = i * 128 + tid;
            int r = idx >> 2, c = (idx & 3) * 8;
            cpasync16(Asb + r * SA + c, Ap + (size_t)r * lda + k0 + c);
            cpasync16(Bsb + r * SA + c, Bp + (size_t)r * ldb + k0 + c);
        }
        asm volatile("cp.async.commit_group;\n");
    };

    constexpr int NT = K / BK;
    load_tile(0, 0);
    load_tile(BK, 1);

    const int rA = (lane >> 2);            // 0..7
    const int kp = (lane & 3) * 2;
    const int aoff  = (wm * 64 + rA) * SA + kp;
    const int boff  = (wn * 64 + rA) * SA + kp;

    #pragma unroll 1
    for (int t = 0; t < NT; t++) {
        if (t + 2 < NT) {
            load_tile((t + 2) * BK, (t + 2) % 3);
            asm volatile("cp.async.wait_group 2;\n");
        } else if (t + 1 < NT) {
            asm volatile("cp.async.wait_group 1;\n");
        } else {
            asm volatile("cp.async.wait_group 0;\n");
        }
        __syncthreads();

        const __nv_bfloat16* Asb = As + (t % 3) * STG;
        const __nv_bfloat16* Bsb = Bs + (t % 3) * STG;

        #pragma unroll
        for (int ks = 0; ks < BK; ks += 16) {
            uint32_t afr[4][4];
            #pragma unroll
            for (int i = 0; i < 4; i++) {
                const __nv_bfloat16* p = Asb + aoff + i * (16 * SA) + ks;
                afr[i][0] = *(const uint32_t*)(p);
                afr[i][1] = *(const uint32_t*)(p + 8 * SA);
                afr[i][2] = *(const uint32_t*)(p + 8);
                afr[i][3] = *(const uint32_t*)(p + 8 * SA + 8);
            }
            uint32_t bfr[8][2];
            #pragma unroll
            for (int j = 0; j < 8; j++) {
                const __nv_bfloat16* p = Bsb + boff + j * (8 * SA) + ks;
                bfr[j][0] = *(const uint32_t*)(p);
                bfr[j][1] = *(const uint32_t*)(p + 8);
            }
            #pragma unroll
            for (int i = 0; i < 4; i++)
                #pragma unroll
                for (int j = 0; j < 8; j++)
                    mma_bf16(acc[i][j], afr[i], bfr[j]);
        }
        __syncthreads();
    }

    // ----- epilogue -----
    const int biasIdx = (MODE == 2) ? (z % aMod) : (z % bMod);
    #pragma unroll
    for (int j = 0; j < 8; j++) {
        int cidx = n_blk + wn * 64 + j * 8 + 2 * (lane & 3);
        float cb0 = 0.f, cb1 = 0.f;
        if (MODE == 1) {
            const float* bp = bias0 + (size_t)biasIdx * D_ + cidx;
            cb0 = bp[0]; cb1 = bp[1];
        }
        #pragma unroll
        for (int i = 0; i < 4; i++) {
            int r0 = m_blk + wm * 64 + i * 16 + (lane >> 2);
            float v0 = acc[i][j][0], v1 = acc[i][j][1];
            float v2 = acc[i][j][2], v3 = acc[i][j][3];
            if (MODE == 1) {
                v0 = fmaxf(v0 + cb0, 0.f) * scale;
                v1 = fmaxf(v1 + cb1, 0.f) * scale;
                v2 = fmaxf(v2 + cb0, 0.f) * scale;
                v3 = fmaxf(v3 + cb1, 0.f) * scale;
            } else if (MODE == 2) {
                float rb0 = bias0[(size_t)biasIdx * D_ + r0];
                float rb1 = bias0[(size_t)biasIdx * D_ + r0 + 8];
                v0 = fmaxf(v0 + rb0, 0.f);
                v1 = fmaxf(v1 + rb0, 0.f);
                v2 = fmaxf(v2 + rb1, 0.f);
                v3 = fmaxf(v3 + rb1, 0.f);
            }
            if (MODE == 3) {
                float* Cp = (float*)C0 + (size_t)z * cB;
                *(float2*)(Cp + (size_t)r0 * ldc + cidx)       = make_float2(v0, v1);
                *(float2*)(Cp + (size_t)(r0 + 8) * ldc + cidx) = make_float2(v2, v3);
            } else {
                __nv_bfloat16* Cp = (__nv_bfloat16*)C0 + (size_t)z * cB;
                *(uint32_t*)(Cp + (size_t)r0 * ldc + cidx)       = packbf(v0, v1);
                *(uint32_t*)(Cp + (size_t)(r0 + 8) * ldc + cidx) = packbf(v2, v3);
            }
        }
    }
}

// ---------------------------------------------------------------------------
// 3) Softmax over bf16 rows of g_scores (len 512), in place. 1 warp / row.
// ---------------------------------------------------------------------------
__global__ void softmax_kernel()
{
    int gw   = (blockIdx.x * blockDim.x + threadIdx.x) >> 5;
    int lane = threadIdx.x & 31;
    if (gw >= B_ * C_ * P_) return;

    uint4* row = reinterpret_cast<uint4*>(g_scores) + (size_t)gw * (P_ / 8);

    uint4 u[2];
    float f[16];
    float m = -1e30f;
    #pragma unroll
    for (int i = 0; i < 2; i++) {
        u[i] = row[lane + 32 * i];
        const __nv_bfloat16* h = (const __nv_bfloat16*)&u[i];
        #pragma unroll
        for (int j = 0; j < 8; j++) {
            float x = __bfloat162float(h[j]);
            f[i * 8 + j] = x;
            m = fmaxf(m, x);
        }
    }
    #pragma unroll
    for (int o = 16; o > 0; o >>= 1)
        m = fmaxf(m, __shfl_xor_sync(0xffffffffu, m, o));

    float s = 0.f;
    #pragma unroll
    for (int i = 0; i < 16; i++) {
        f[i] = __expf(f[i] - m);
        s += f[i];
    }
    #pragma unroll
    for (int o = 16; o > 0; o >>= 1)
        s += __shfl_xor_sync(0xffffffffu, s, o);

    float inv = 1.0f / s;
    #pragma unroll
    for (int i = 0; i < 2; i++) {
        uint32_t* w = (uint32_t*)&u[i];
        #pragma unroll
        for (int j = 0; j < 4; j++)
            w[j] = packbf(f[i * 8 + j * 2] * inv, f[i * 8 + j * 2 + 1] * inv);
        row[lane + 32 * i] = u[i];
    }
}

// ---------------------------------------------------------------------------
// launch
// ---------------------------------------------------------------------------
extern "C" void kernel_launch(void* const* d_in, const int* in_sizes, int n_in,
                              void* d_out, int out_size)
{
    const float* query = (const float*)d_in[0];
    const float* aw    = (const float*)d_in[1];
    const float* wq    = (const float*)d_in[2];
    const float* wk    = (const float*)d_in[3];
    const float* wv    = (const float*)d_in[4];
    const float* bq    = (const float*)d_in[5];
    const float* bk    = (const float*)d_in[6];
    const float* bv    = (const float*)d_in[7];
    float* out = (float*)d_out;

    __nv_bfloat16 *gctx, *gqr, *gq, *gk, *gvT, *gsc, *gwqT, *gwkT, *gwvT;
    cudaGetSymbolAddress((void**)&gctx, g_context);
    cudaGetSymbolAddress((void**)&gqr, g_qr);
    cudaGetSymbolAddress((void**)&gq, g_q);
    cudaGetSymbolAddress((void**)&gk, g_k);
    cudaGetSymbolAddress((void**)&gvT, g_vT);
    cudaGetSymbolAddress((void**)&gsc, g_scores);
    cudaGetSymbolAddress((void**)&gwqT, g_wqT);
    cudaGetSymbolAddress((void**)&gwkT, g_wkT);
    cudaGetSymbolAddress((void**)&gwvT, g_wvT);

    constexpr int SMEM_BYTES = 6 * 128 * 40 * 2;   // 61440
    cudaFuncSetAttribute(mma_gemm<D_, 1>, cudaFuncAttributeMaxDynamicSharedMemorySize, SMEM_BYTES);
    cudaFuncSetAttribute(mma_gemm<D_, 2>, cudaFuncAttributeMaxDynamicSharedMemorySize, SMEM_BYTES);
    cudaFuncSetAttribute(mma_gemm<D_, 0>, cudaFuncAttributeMaxDynamicSharedMemorySize, SMEM_BYTES);
    cudaFuncSetAttribute(mma_gemm<P_, 3>, cudaFuncAttributeMaxDynamicSharedMemorySize, SMEM_BYTES);

    const float qscale = 1.0f / 16.0f;   // D^-0.5
    const size_t PD = (size_t)P_ * D_;
    const size_t PP = (size_t)P_ * P_;
    const size_t DD = (size_t)D_ * D_;
    const int BC = B_ * C_;

    // 0) transpose weights to bf16 [c][e][d]
    transpose_w_kernel<<<dim3(8, 8, 3 * C_), dim3(32, 8)>>>(wq, wk, wv);

    // 1) context + query (bf16)
    context_kernel<<<(B_ * P_ * D_ / 2 + 255) / 256, 256>>>(query, aw);

    // 2) q-proj: A=qr[z] (512x256), B=wqT[c] (256x256); col-bias+relu+scale
    mma_gemm<D_, 1><<<dim3(4, 2, BC), 128, SMEM_BYTES>>>(gqr, gwqT, bq, gq,
        D_, D_, D_, PD, DD, PD, BC, C_, qscale);
    //    k-proj
    mma_gemm<D_, 1><<<dim3(4, 2, BC), 128, SMEM_BYTES>>>(gctx, gwkT, bk, gk,
        D_, D_, D_, PD, DD, PD, BC, C_, 1.0f);
    //    vT-proj: A=wvT[c] (256x256), B=ctx[z] (512x256) -> vT[e][p]; row-bias+relu
    mma_gemm<D_, 2><<<dim3(2, 4, BC), 128, SMEM_BYTES>>>(gwvT, gctx, bv, gvT,
        D_, D_, P_, DD, PD, PD, C_, BC, 1.0f);

    // 3) scores = q @ k^T : 512x512x256, bf16 out
    mma_gemm<D_, 0><<<dim3(4, 4, BC), 128, SMEM_BYTES>>>(gq, gk, nullptr, gsc,
        D_, D_, P_, PD, PD, PP, BC, BC, 1.0f);

    // 4) softmax in-place on bf16 scores
    softmax_kernel<<<(B_ * C_ * P_) / 8, 256>>>();

    // 5) out = attn @ vT^T : A=attn (512x512), B=vT (256x512), fp32 out
    mma_gemm<P_, 3><<<dim3(4, 2, BC), 128, SMEM_BYTES>>>(gsc, gvT, nullptr, out,
        P_, P_, D_, PP, PD, PD, BC, BC, 1.0f);
}

// round 11
// speedup vs baseline: 1.8755x; 1.0646x over previous
#include <cuda_runtime.h>
#include <cuda_bf16.h>
#include <math.h>
#include <stdint.h>

static constexpr int B_ = 16, C_ = 16, P_ = 512, D_ = 256;

// Scratch (device globals; allocation in kernel_launch is forbidden)
__device__ __nv_bfloat16 g_context[(size_t)B_ * C_ * P_ * D_];  // [b,c][p][d]
__device__ __nv_bfloat16 g_qr[(size_t)B_ * C_ * P_ * D_];       // [b,c][p][d]
__device__ __nv_bfloat16 g_q[(size_t)B_ * C_ * P_ * D_];        // [b,c][p][e]
__device__ __nv_bfloat16 g_k[(size_t)B_ * C_ * P_ * D_];        // [b,c][p][e]
__device__ __nv_bfloat16 g_vT[(size_t)B_ * C_ * P_ * D_];       // [b,c][e][p]
__device__ __nv_bfloat16 g_scores[(size_t)B_ * C_ * P_ * P_];   // [b,c][p][q]
__device__ __nv_bfloat16 g_wqT[(size_t)C_ * D_ * D_];           // [c][e][d]
__device__ __nv_bfloat16 g_wkT[(size_t)C_ * D_ * D_];
__device__ __nv_bfloat16 g_wvT[(size_t)C_ * D_ * D_];

// ---------------------------------------------------------------------------
// helpers
// ---------------------------------------------------------------------------
__device__ __forceinline__ uint32_t smem_u32(const void* p) {
    uint32_t a;
    asm("{ .reg .u64 t; cvta.to.shared.u64 t, %1; cvt.u32.u64 %0, t; }"
        : "=r"(a) : "l"(p));
    return a;
}
__device__ __forceinline__ void cpasync16(void* smem, const void* gmem) {
    unsigned s = (unsigned)__cvta_generic_to_shared(smem);
    asm volatile("cp.async.cg.shared.global [%0], [%1], 16;\n" :: "r"(s), "l"(gmem));
}
__device__ __forceinline__ void mma_bf16(float* c, const uint32_t* a, const uint32_t* b) {
    asm volatile(
        "mma.sync.aligned.m16n8k16.row.col.f32.bf16.bf16.f32 "
        "{%0,%1,%2,%3}, {%4,%5,%6,%7}, {%8,%9}, {%0,%1,%2,%3};"
        : "+f"(c[0]), "+f"(c[1]), "+f"(c[2]), "+f"(c[3])
        : "r"(a[0]), "r"(a[1]), "r"(a[2]), "r"(a[3]), "r"(b[0]), "r"(b[1]));
}
__device__ __forceinline__ void ldsm4(uint32_t& r0, uint32_t& r1,
                                      uint32_t& r2, uint32_t& r3, uint32_t addr) {
    asm volatile("ldmatrix.sync.aligned.m8n8.x4.shared.b16 {%0,%1,%2,%3}, [%4];"
                 : "=r"(r0), "=r"(r1), "=r"(r2), "=r"(r3) : "r"(addr));
}
__device__ __forceinline__ uint32_t packbf(float x, float y) {
    __nv_bfloat162 h = __floats2bfloat162_rn(x, y);
    return *(uint32_t*)&h;
}

// ---------------------------------------------------------------------------
// 0) transpose weights to bf16 [c][e][d]
// ---------------------------------------------------------------------------
__global__ void transpose_w_kernel(const float* __restrict__ wq,
                                   const float* __restrict__ wk,
                                   const float* __restrict__ wv)
{
    __shared__ float tile[32][33];
    int which = blockIdx.z / C_;
    int c     = blockIdx.z % C_;
    const float* src = (which == 0) ? wq : (which == 1) ? wk : wv;
    __nv_bfloat16* dst = (which == 0) ? g_wqT : (which == 1) ? g_wkT : g_wvT;
    src += (size_t)c * D_ * D_;
    dst += (size_t)c * D_ * D_;

    int x0 = blockIdx.x * 32;   // d
    int y0 = blockIdx.y * 32;   // e
    int tx = threadIdx.x, ty = threadIdx.y;
    #pragma unroll
    for (int j = 0; j < 4; j++)
        tile[ty + 8 * j][tx] = src[(size_t)(x0 + ty + 8 * j) * D_ + y0 + tx];
    __syncthreads();
    #pragma unroll
    for (int j = 0; j < 4; j++)
        dst[(size_t)(y0 + ty + 8 * j) * D_ + x0 + tx] =
            __float2bfloat16(tile[tx][ty + 8 * j]);
}

// ---------------------------------------------------------------------------
// 1) context = rowsum-over-C(aw*q) - aw*q, bf16 out; also bf16 query copy
// ---------------------------------------------------------------------------
__global__ void context_kernel(const float* __restrict__ query,
                               const float* __restrict__ aw)
{
    int idx = blockIdx.x * blockDim.x + threadIdx.x;   // over B*P*D/2 (pairs)
    if (idx >= B_ * P_ * D_ / 2) return;
    int b  = idx / (P_ * D_ / 2);
    int pd = (idx - b * (P_ * D_ / 2)) * 2;

    const float* qb  = query + (size_t)b * C_ * P_ * D_ + pd;
    const float* awp = aw + pd;

    float q0[C_], q1[C_], a0[C_], a1[C_];
    float s0 = 0.f, s1 = 0.f;
    #pragma unroll
    for (int c = 0; c < C_; c++) {
        float2 q = *(const float2*)(qb + (size_t)c * P_ * D_);
        float2 w = *(const float2*)(awp + (size_t)c * P_ * D_);
        q0[c] = q.x; q1[c] = q.y;
        a0[c] = w.x * q.x; a1[c] = w.y * q.y;
        s0 += a0[c]; s1 += a1[c];
    }
    __nv_bfloat16* ctx = g_context + (size_t)b * C_ * P_ * D_ + pd;
    __nv_bfloat16* qr  = g_qr + (size_t)b * C_ * P_ * D_ + pd;
    #pragma unroll
    for (int c = 0; c < C_; c++) {
        *(uint32_t*)(ctx + (size_t)c * P_ * D_) = packbf(s0 - a0[c], s1 - a1[c]);
        *(uint32_t*)(qr + (size_t)c * P_ * D_)  = packbf(q0[c], q1[c]);
    }
}

// ---------------------------------------------------------------------------
// 2) Unified batched bf16 GEMM: C[z] = A[z%aMod](MxK) * B[z%bMod](NxK)^T
//    All operands bf16 k-major. CTA 128x128, BK=32, 3-stage cp.async,
//    4 warps, 64x64 warp tile, m16n8k16, ldmatrix.x4 fragment loads.
//    MODE 0: bf16 store. MODE 1: col-bias+relu+scale, bf16. MODE 2: row-bias
//    +relu, bf16. MODE 3: fp32 store.
// ---------------------------------------------------------------------------
template<int K, int MODE>
__global__ __launch_bounds__(128, 2)
void mma_gemm(const __nv_bfloat16* __restrict__ A0,
              const __nv_bfloat16* __restrict__ B0,
              const float* __restrict__ bias0, void* __restrict__ C0,
              int lda, int ldb, int ldc,
              size_t aB, size_t bB, size_t cB,
              int aMod, int bMod, float scale)
{
    constexpr int BK = 32;
    constexpr int SA = 40;                 // bf16 elems per smem row (pad 8)
    constexpr int STG = 128 * SA;          // per operand per stage

    extern __shared__ __nv_bfloat16 sh[];
    __nv_bfloat16* As = sh;                // 3 stages
    __nv_bfloat16* Bs = sh + 3 * STG;

    const int tid  = threadIdx.x;
    const int lane = tid & 31;
    const int warp = tid >> 5;             // 0..3
    const int wm = warp >> 1;              // 0..1
    const int wn = warp & 1;               // 0..1
    const int z  = blockIdx.z;
    const int m_blk = blockIdx.x * 128;
    const int n_blk = blockIdx.y * 128;

    const __nv_bfloat16* Ap = A0 + (size_t)(z % aMod) * aB + (size_t)m_blk * lda;
    const __nv_bfloat16* Bp = B0 + (size_t)(z % bMod) * bB + (size_t)n_blk * ldb;

    float acc[4][8][4];
    #pragma unroll
    for (int i = 0; i < 4; i++)
        #pragma unroll
        for (int j = 0; j < 8; j++)
            #pragma unroll
            for (int r = 0; r < 4; r++) acc[i][j][r] = 0.f;

    auto load_tile = [&](int k0, int buf) {
        __nv_bfloat16* Asb = As + buf * STG;
        __nv_bfloat16* Bsb = Bs + buf * STG;
        #pragma unroll
        for (int i = 0; i < 4; i++) {
            int idx = i * 128 + tid;
            int r = idx >> 2, c = (idx & 3) * 8;
            cpasync16(Asb + r * SA + c, Ap + (size_t)r * lda + k0 + c);
            cpasync16(Bsb + r * SA + c, Bp + (size_t)r * ldb + k0 + c);
        }
        asm volatile("cp.async.commit_group;\n");
    };

    constexpr int NT = K / BK;
    load_tile(0, 0);
    load_tile(BK, 1);

    // ldmatrix base addresses (bytes, warp/lane constant)
    const int g  = lane >> 3;              // 0..3 (matrix group)
    const int rw = lane & 7;
    const uint32_t smA = smem_u32(As);
    const uint32_t smB = smem_u32(Bs);
    // A: matrices (r0k0, r8k0, r0k8, r8k8): row = wm*64 + (g&1)*8 + rw, k = (g>>1)*8
    const uint32_t aBase = smA + ((uint32_t)((wm * 64 + (g & 1) * 8 + rw) * SA
                                             + (g >> 1) * 8) << 1);
    // B: matrices (n0k0, n0k8, n8k0, n8k8): n = wn*64 + (g>>1)*8 + rw, k = (g&1)*8
    const uint32_t bBase = smB + ((uint32_t)((wn * 64 + (g >> 1) * 8 + rw) * SA
                                             + (g & 1) * 8) << 1);

    #pragma unroll 1
    for (int t = 0; t < NT; t++) {
        if (t + 2 < NT) {
            load_tile((t + 2) * BK, (t + 2) % 3);
            asm volatile("cp.async.wait_group 2;\n");
        } else if (t + 1 < NT) {
            asm volatile("cp.async.wait_group 1;\n");
        } else {
            asm volatile("cp.async.wait_group 0;\n");
        }
        __syncthreads();

        const uint32_t stOff = (uint32_t)((t % 3) * STG) << 1;
        const uint32_t sA = aBase + stOff;
        const uint32_t sB = bBase + stOff;

        #pragma unroll
        for (int ks = 0; ks < BK; ks += 16) {
            uint32_t afr[4][4];
            #pragma unroll
            for (int i = 0; i < 4; i++)
                ldsm4(afr[i][0], afr[i][1], afr[i][2], afr[i][3],
                      sA + (uint32_t)((i * 16 * SA + ks) << 1));
            uint32_t bfr[8][2];
            #pragma unroll
            for (int j2 = 0; j2 < 4; j2++)
                ldsm4(bfr[2 * j2][0], bfr[2 * j2][1],
                      bfr[2 * j2 + 1][0], bfr[2 * j2 + 1][1],
                      sB + (uint32_t)((j2 * 16 * SA + ks) << 1));
            #pragma unroll
            for (int i = 0; i < 4; i++)
                #pragma unroll
                for (int j = 0; j < 8; j++)
                    mma_bf16(acc[i][j], afr[i], bfr[j]);
        }
        __syncthreads();
    }

    // ----- epilogue -----
    const int biasIdx = (MODE == 2) ? (z % aMod) : (z % bMod);
    #pragma unroll
    for (int j = 0; j < 8; j++) {
        int cidx = n_blk + wn * 64 + j * 8 + 2 * (lane & 3);
        float cb0 = 0.f, cb1 = 0.f;
        if (MODE == 1) {
            const float* bp = bias0 + (size_t)biasIdx * D_ + cidx;
            cb0 = bp[0]; cb1 = bp[1];
        }
        #pragma unroll
        for (int i = 0; i < 4; i++) {
            int r0 = m_blk + wm * 64 + i * 16 + (lane >> 2);
            float v0 = acc[i][j][0], v1 = acc[i][j][1];
            float v2 = acc[i][j][2], v3 = acc[i][j][3];
            if (MODE == 1) {
                v0 = fmaxf(v0 + cb0, 0.f) * scale;
                v1 = fmaxf(v1 + cb1, 0.f) * scale;
                v2 = fmaxf(v2 + cb0, 0.f) * scale;
                v3 = fmaxf(v3 + cb1, 0.f) * scale;
            } else if (MODE == 2) {
                float rb0 = bias0[(size_t)biasIdx * D_ + r0];
                float rb1 = bias0[(size_t)biasIdx * D_ + r0 + 8];
                v0 = fmaxf(v0 + rb0, 0.f);
                v1 = fmaxf(v1 + rb0, 0.f);
                v2 = fmaxf(v2 + rb1, 0.f);
                v3 = fmaxf(v3 + rb1, 0.f);
            }
            if (MODE == 3) {
                float* Cp = (float*)C0 + (size_t)z * cB;
                *(float2*)(Cp + (size_t)r0 * ldc + cidx)       = make_float2(v0, v1);
                *(float2*)(Cp + (size_t)(r0 + 8) * ldc + cidx) = make_float2(v2, v3);
            } else {
                __nv_bfloat16* Cp = (__nv_bfloat16*)C0 + (size_t)z * cB;
                *(uint32_t*)(Cp + (size_t)r0 * ldc + cidx)       = packbf(v0, v1);
                *(uint32_t*)(Cp + (size_t)(r0 + 8) * ldc + cidx) = packbf(v2, v3);
            }
        }
    }
}

// ---------------------------------------------------------------------------
// 3) Softmax over bf16 rows of g_scores (len 512), in place. 1 warp / row.
// ---------------------------------------------------------------------------
__global__ void softmax_kernel()
{
    int gw   = (blockIdx.x * blockDim.x + threadIdx.x) >> 5;
    int lane = threadIdx.x & 31;
    if (gw >= B_ * C_ * P_) return;

    uint4* row = reinterpret_cast<uint4*>(g_scores) + (size_t)gw * (P_ / 8);

    uint4 u[2];
    float f[16];
    float m = -1e30f;
    #pragma unroll
    for (int i = 0; i < 2; i++) {
        u[i] = row[lane + 32 * i];
        const __nv_bfloat16* h = (const __nv_bfloat16*)&u[i];
        #pragma unroll
        for (int j = 0; j < 8; j++) {
            float x = __bfloat162float(h[j]);
            f[i * 8 + j] = x;
            m = fmaxf(m, x);
        }
    }
    #pragma unroll
    for (int o = 16; o > 0; o >>= 1)
        m = fmaxf(m, __shfl_xor_sync(0xffffffffu, m, o));

    float s = 0.f;
    #pragma unroll
    for (int i = 0; i < 16; i++) {
        f[i] = __expf(f[i] - m);
        s += f[i];
    }
    #pragma unroll
    for (int o = 16; o > 0; o >>= 1)
        s += __shfl_xor_sync(0xffffffffu, s, o);

    float inv = 1.0f / s;
    #pragma unroll
    for (int i = 0; i < 2; i++) {
        uint32_t* w = (uint32_t*)&u[i];
        #pragma unroll
        for (int j = 0; j < 4; j++)
            w[j] = packbf(f[i * 8 + j * 2] * inv, f[i * 8 + j * 2 + 1] * inv);
        row[lane + 32 * i] = u[i];
    }
}

// ---------------------------------------------------------------------------
// launch
// ---------------------------------------------------------------------------
extern "C" void kernel_launch(void* const* d_in, const int* in_sizes, int n_in,
                              void* d_out, int out_size)
{
    const float* query = (const float*)d_in[0];
    const float* aw    = (const float*)d_in[1];
    const float* wq    = (const float*)d_in[2];
    const float* wk    = (const float*)d_in[3];
    const float* wv    = (const float*)d_in[4];
    const float* bq    = (const float*)d_in[5];
    const float* bk    = (const float*)d_in[6];
    const float* bv    = (const float*)d_in[7];
    float* out = (float*)d_out;

    __nv_bfloat16 *gctx, *gqr, *gq, *gk, *gvT, *gsc, *gwqT, *gwkT, *gwvT;
    cudaGetSymbolAddress((void**)&gctx, g_context);
    cudaGetSymbolAddress((void**)&gqr, g_qr);
    cudaGetSymbolAddress((void**)&gq, g_q);
    cudaGetSymbolAddress((void**)&gk, g_k);
    cudaGetSymbolAddress((void**)&gvT, g_vT);
    cudaGetSymbolAddress((void**)&gsc, g_scores);
    cudaGetSymbolAddress((void**)&gwqT, g_wqT);
    cudaGetSymbolAddress((void**)&gwkT, g_wkT);
    cudaGetSymbolAddress((void**)&gwvT, g_wvT);

    constexpr int SMEM_BYTES = 6 * 128 * 40 * 2;   // 61440
    cudaFuncSetAttribute(mma_gemm<D_, 1>, cudaFuncAttributeMaxDynamicSharedMemorySize, SMEM_BYTES);
    cudaFuncSetAttribute(mma_gemm<D_, 2>, cudaFuncAttributeMaxDynamicSharedMemorySize, SMEM_BYTES);
    cudaFuncSetAttribute(mma_gemm<D_, 0>, cudaFuncAttributeMaxDynamicSharedMemorySize, SMEM_BYTES);
    cudaFuncSetAttribute(mma_gemm<P_, 3>, cudaFuncAttributeMaxDynamicSharedMemorySize, SMEM_BYTES);

    const float qscale = 1.0f / 16.0f;   // D^-0.5
    const size_t PD = (size_t)P_ * D_;
    const size_t PP = (size_t)P_ * P_;
    const size_t DD = (size_t)D_ * D_;
    const int BC = B_ * C_;

    // 0) transpose weights to bf16 [c][e][d]
    transpose_w_kernel<<<dim3(8, 8, 3 * C_), dim3(32, 8)>>>(wq, wk, wv);

    // 1) context + query (bf16)
    context_kernel<<<(B_ * P_ * D_ / 2 + 255) / 256, 256>>>(query, aw);

    // 2) q-proj: A=qr[z] (512x256), B=wqT[c] (256x256); col-bias+relu+scale
    mma_gemm<D_, 1><<<dim3(4, 2, BC), 128, SMEM_BYTES>>>(gqr, gwqT, bq, gq,
        D_, D_, D_, PD, DD, PD, BC, C_, qscale);
    //    k-proj
    mma_gemm<D_, 1><<<dim3(4, 2, BC), 128, SMEM_BYTES>>>(gctx, gwkT, bk, gk,
        D_, D_, D_, PD, DD, PD, BC, C_, 1.0f);
    //    vT-proj: A=wvT[c] (256x256), B=ctx[z] (512x256) -> vT[e][p]; row-bias+relu
    mma_gemm<D_, 2><<<dim3(2, 4, BC), 128, SMEM_BYTES>>>(gwvT, gctx, bv, gvT,
        D_, D_, P_, DD, PD, PD, C_, BC, 1.0f);

    // 3) scores = q @ k^T : 512x512x256, bf16 out
    mma_gemm<D_, 0><<<dim3(4, 4, BC), 128, SMEM_BYTES>>>(gq, gk, nullptr, gsc,
        D_, D_, P_, PD, PD, PP, BC, BC, 1.0f);

    // 4) softmax in-place on bf16 scores
    softmax_kernel<<<(B_ * C_ * P_) / 8, 256>>>();

    // 5) out = attn @ vT^T : A=attn (512x512), B=vT (256x512), fp32 out
    mma_gemm<P_, 3><<<dim3(4, 2, BC), 128, SMEM_BYTES>>>(gsc, gvT, nullptr, out,
        P_, P_, D_, PP, PD, PD, BC, BC, 1.0f);
}